// round 1
// baseline (speedup 1.0000x reference)
#include <cuda_runtime.h>
#include <math_constants.h>

#define K 8
#define D 8
#define TRI 36              // D*(D+1)/2
#define PHI_DIM 360         // K + K*D + K*TRI
#define M_MODELS 32
#define N_POINTS 32768
#define CHUNKS 16
#define THREADS 256
#define PPT 4               // points per thread per iteration
#define ITERS 2             // (N_POINTS/CHUNKS) / (THREADS*PPT)
#define PSTRIDE 45          // per-(m,k) params: 36 Linv + 8 mu + 1 const

// Scratch (no allocations allowed)
__device__ float g_params[M_MODELS * K * PSTRIDE];
__device__ float g_prior[M_MODELS];
__device__ float g_partial[M_MODELS * CHUNKS];

__host__ __device__ __forceinline__ constexpr int tidx(int i, int j) {
    return i * (i + 1) / 2 + j;
}

// ---------------------------------------------------------------------------
// Precompute: per (m,k) invert the lower-triangular L, fold the 0.5*log2(e)
// scale into Linv, build the per-component log2-domain constant, and compute
// the prior term. 32 blocks x 32 threads; negligible runtime.
// ---------------------------------------------------------------------------
__global__ void precompute_kernel(const float* __restrict__ phi) {
    const int m = blockIdx.x;
    const float* pm = phi + m * PHI_DIM;
    const int lane = threadIdx.x;

    // prior: sum(phi^2) over the 360-vector
    float ps = 0.f;
    for (int t = lane; t < PHI_DIM; t += 32) {
        float v = pm[t];
        ps = fmaf(v, v, ps);
    }
    #pragma unroll
    for (int o = 16; o; o >>= 1) ps += __shfl_xor_sync(0xffffffffu, ps, o);
    if (lane == 0) g_prior[m] = ps;

    if (lane < K) {
        const int k = lane;

        // log_softmax of pi_tilde (each of 8 lanes reads all 8 values)
        float mx = -CUDART_INF_F;
        #pragma unroll
        for (int j = 0; j < K; ++j) mx = fmaxf(mx, pm[j]);
        float s = 0.f;
        #pragma unroll
        for (int j = 0; j < K; ++j) s += expf(pm[j] - mx);
        const float log_pi = pm[k] - mx - logf(s);

        float L[TRI];
        #pragma unroll
        for (int t = 0; t < TRI; ++t) L[t] = pm[K + K * D + k * TRI + t];

        // log-det with the reference's clip(|diag|, 1e-8)
        float ld = 0.f;
        #pragma unroll
        for (int i = 0; i < D; ++i)
            ld += logf(fmaxf(fabsf(L[tidx(i, i)]), 1e-8f));
        ld *= 2.f;

        // c = log_pi - 0.5*(D*log(2pi) + log_det)
        const float c = log_pi - 0.5f * (D * 1.8378770664093453f + ld);

        // invert lower-triangular L (forward substitution, column by column)
        float Inv[TRI];
        #pragma unroll
        for (int j = 0; j < D; ++j) {
            Inv[tidx(j, j)] = 1.f / L[tidx(j, j)];
            #pragma unroll
            for (int i = j + 1; i < D; ++i) {
                float acc = 0.f;
                #pragma unroll
                for (int p = j; p < i; ++p)
                    acc = fmaf(L[tidx(i, p)], Inv[tidx(p, j)], acc);
                Inv[tidx(i, j)] = -acc / L[tidx(i, i)];
            }
        }

        // Fold sqrt(0.5*log2(e)) into Linv so maha comes out pre-scaled for exp2
        const float SCALE = 0.84932375f;  // sqrt(0.5 * 1.4426950408889634)
        float* dst = g_params + (m * K + k) * PSTRIDE;
        #pragma unroll
        for (int t = 0; t < TRI; ++t) dst[t] = Inv[t] * SCALE;
        #pragma unroll
        for (int d = 0; d < D; ++d) dst[TRI + d] = pm[K + k * D + d];
        dst[TRI + D] = c * 1.4426950408889634f;  // constant in log2 domain
    }
}

// ---------------------------------------------------------------------------
// Main: grid = M_MODELS*CHUNKS blocks. Each block: one model, one slice of X.
// Register tile of PPT=4 points per thread; streaming logsumexp in log2 domain.
// ---------------------------------------------------------------------------
__global__ void __launch_bounds__(THREADS) main_kernel(const float* __restrict__ X) {
    const int m = blockIdx.x / CHUNKS;
    const int chunk = blockIdx.x % CHUNKS;

    __shared__ float sp[K * PSTRIDE];
    for (int t = threadIdx.x; t < K * PSTRIDE; t += THREADS)
        sp[t] = g_params[m * K * PSTRIDE + t];
    __syncthreads();

    float acc = 0.f;
    const int base = chunk * (N_POINTS / CHUNKS);

    #pragma unroll 1
    for (int it = 0; it < ITERS; ++it) {
        const int n0 = base + it * (THREADS * PPT) + threadIdx.x;

        float x[PPT][D];
        #pragma unroll
        for (int p = 0; p < PPT; ++p) {
            const float4* xp =
                reinterpret_cast<const float4*>(X + (size_t)(n0 + p * THREADS) * D);
            float4 a = xp[0], b = xp[1];
            x[p][0] = a.x; x[p][1] = a.y; x[p][2] = a.z; x[p][3] = a.w;
            x[p][4] = b.x; x[p][5] = b.y; x[p][6] = b.z; x[p][7] = b.w;
        }

        float mx[PPT], sm[PPT];
        #pragma unroll
        for (int p = 0; p < PPT; ++p) { mx[p] = -CUDART_INF_F; sm[p] = 0.f; }

        #pragma unroll 1
        for (int k = 0; k < K; ++k) {
            const float* pk = sp + k * PSTRIDE;
            float w[PSTRIDE];
            #pragma unroll
            for (int t = 0; t < PSTRIDE; ++t) w[t] = pk[t];

            #pragma unroll
            for (int p = 0; p < PPT; ++p) {
                float d[D];
                #pragma unroll
                for (int i = 0; i < D; ++i) d[i] = x[p][i] - w[TRI + i];
                float maha = 0.f;
                #pragma unroll
                for (int i = 0; i < D; ++i) {
                    float a = 0.f;
                    #pragma unroll
                    for (int j = 0; j <= i; ++j)
                        a = fmaf(w[tidx(i, j)], d[j], a);
                    maha = fmaf(a, a, maha);
                }
                // logit in log2 domain (maha already scaled by 0.5*log2e)
                const float l2 = w[TRI + D] - maha;
                const float nm = fmaxf(mx[p], l2);
                sm[p] = sm[p] * exp2f(mx[p] - nm) + exp2f(l2 - nm);
                mx[p] = nm;
            }
        }

        #pragma unroll
        for (int p = 0; p < PPT; ++p)
            acc += (mx[p] + log2f(sm[p])) * 0.6931471805599453f;
    }

    // deterministic block reduction
    __shared__ float red[THREADS];
    red[threadIdx.x] = acc;
    __syncthreads();
    #pragma unroll
    for (int s = THREADS / 2; s > 0; s >>= 1) {
        if (threadIdx.x < s) red[threadIdx.x] += red[threadIdx.x + s];
        __syncthreads();
    }
    if (threadIdx.x == 0) g_partial[m * CHUNKS + chunk] = red[0];
}

// ---------------------------------------------------------------------------
// Finalize: out[m] = -sum_chunks partial + 0.005 * prior[m]
// ---------------------------------------------------------------------------
__global__ void finalize_kernel(float* __restrict__ out) {
    const int m = threadIdx.x;
    if (m < M_MODELS) {
        double s = 0.0;
        #pragma unroll
        for (int c = 0; c < CHUNKS; ++c) s += (double)g_partial[m * CHUNKS + c];
        out[m] = (float)(-s + 0.005 * (double)g_prior[m]);  // 0.5 * LAMBDA_PRIOR
    }
}

extern "C" void kernel_launch(void* const* d_in, const int* in_sizes, int n_in,
                              void* d_out, int out_size) {
    const float* phi = (const float*)d_in[0];  // (32, 360)
    const float* X   = (const float*)d_in[1];  // (32768, 8)
    float* out = (float*)d_out;                // (32,)

    precompute_kernel<<<M_MODELS, 32>>>(phi);
    main_kernel<<<M_MODELS * CHUNKS, THREADS>>>(X);
    finalize_kernel<<<1, 32>>>(out);
}

// round 2
// speedup vs baseline: 1.1012x; 1.1012x over previous
#include <cuda_runtime.h>
#include <math_constants.h>

#define K 8
#define D 8
#define TRI 36              // D*(D+1)/2
#define PHI_DIM 360         // K + K*D + K*TRI
#define M_MODELS 32
#define N_POINTS 32768
#define CHUNKS 16
#define THREADS 256
#define PPT 4               // points per thread per iteration (2 packed pairs)
#define ITERS 2             // (N_POINTS/CHUNKS) / (THREADS*PPT)
#define PSTRIDE 45          // per-(m,k): 36 Linv + 8 (-mu) + 1 const(log2)

typedef unsigned long long ull;

// Scratch (no allocations allowed). Params stored as duplicated float pairs
// so one LDS.64 yields a broadcast-packed f32x2 operand.
__device__ ull   g_params2[M_MODELS * K * PSTRIDE];
__device__ float g_prior[M_MODELS];
__device__ float g_partial[M_MODELS * CHUNKS];

__host__ __device__ __forceinline__ constexpr int tidx(int i, int j) {
    return i * (i + 1) / 2 + j;
}

// ---- packed f32x2 helpers (FFMA2 path: only reachable via PTX) ------------
__device__ __forceinline__ ull pk2(float lo, float hi) {
    ull r; asm("mov.b64 %0,{%1,%2};" : "=l"(r) : "f"(lo), "f"(hi)); return r;
}
__device__ __forceinline__ void up2(ull v, float& lo, float& hi) {
    asm("mov.b64 {%0,%1},%2;" : "=f"(lo), "=f"(hi) : "l"(v));
}
__device__ __forceinline__ ull fma2(ull a, ull b, ull c) {
    ull r; asm("fma.rn.f32x2 %0,%1,%2,%3;" : "=l"(r) : "l"(a), "l"(b), "l"(c)); return r;
}
__device__ __forceinline__ ull add2p(ull a, ull b) {
    ull r; asm("add.rn.f32x2 %0,%1,%2;" : "=l"(r) : "l"(a), "l"(b)); return r;
}
__device__ __forceinline__ ull mul2p(ull a, ull b) {
    ull r; asm("mul.rn.f32x2 %0,%1,%2;" : "=l"(r) : "l"(a), "l"(b)); return r;
}
__device__ __forceinline__ float ex2a(float x) {
    float r; asm("ex2.approx.ftz.f32 %0,%1;" : "=f"(r) : "f"(x)); return r;
}
__device__ __forceinline__ float lg2a(float x) {
    float r; asm("lg2.approx.ftz.f32 %0,%1;" : "=f"(r) : "f"(x)); return r;
}

// ---------------------------------------------------------------------------
// Precompute: grid=32 (one block per model), block=64 threads.
// Thread t = (k, j): owns column j of component k's Linv (parallel forward
// substitution, MUFU-based divisions/logs). Also computes the prior.
// ---------------------------------------------------------------------------
__global__ void precompute_kernel(const float* __restrict__ phi) {
    const int m = blockIdx.x;
    const float* pm = phi + m * PHI_DIM;
    const int t = threadIdx.x;

    // prior = sum(phi^2)
    float ps = 0.f;
    for (int i = t; i < PHI_DIM; i += 64) {
        float v = pm[i];
        ps = fmaf(v, v, ps);
    }
    __shared__ float red[64];
    red[t] = ps;
    __syncthreads();
    #pragma unroll
    for (int s = 32; s > 0; s >>= 1) {
        if (t < s) red[t] += red[t + s];
        __syncthreads();
    }
    if (t == 0) g_prior[m] = red[0];

    const int k = t >> 3;
    const int j = t & 7;
    const float* Lk = pm + K + K * D + k * TRI;
    ull* dst = g_params2 + (m * K + k) * PSTRIDE;

    // sqrt(0.5 * log2(e)): fold into Linv so maha is pre-scaled for exp2
    const float SCALE = 0.8493218002880191f;

    // column-j forward substitution of the triangular inverse
    float col[D];
    col[j] = __fdividef(1.f, Lk[tidx(j, j)]);
    for (int i = j + 1; i < D; ++i) {
        float acc = 0.f;
        for (int p = j; p < i; ++p)
            acc = fmaf(Lk[tidx(i, p)], col[p], acc);
        col[i] = -acc * __fdividef(1.f, Lk[tidx(i, i)]);
    }
    for (int i = j; i < D; ++i) {
        float v = col[i] * SCALE;
        dst[tidx(i, j)] = pk2(v, v);
    }

    // negated mean (so main kernel uses add.f32x2)
    {
        float nm = -pm[K + k * D + j];
        dst[TRI + j] = pk2(nm, nm);
    }

    // per-component constant (log2 domain)
    if (j == 0) {
        float mx = -CUDART_INF_F;
        #pragma unroll
        for (int q = 0; q < K; ++q) mx = fmaxf(mx, pm[q]);
        float s = 0.f;
        #pragma unroll
        for (int q = 0; q < K; ++q) s += __expf(pm[q] - mx);
        const float log_pi = pm[k] - mx - __logf(s);

        float ld = 0.f;
        #pragma unroll
        for (int i = 0; i < D; ++i)
            ld += __logf(fmaxf(fabsf(Lk[tidx(i, i)]), 1e-8f));
        ld *= 2.f;

        const float c = log_pi - 0.5f * (D * 1.8378770664093453f + ld);
        const float c2 = c * 1.4426950408889634f;
        dst[TRI + D] = pk2(c2, c2);
    }
}

// ---------------------------------------------------------------------------
// Main: grid = M_MODELS*CHUNKS blocks x 256 threads. Each thread carries 4
// points as 2 packed f32x2 pairs; maha via FFMA2; streaming logsumexp in
// log2 domain with raw MUFU ex2/lg2.
// ---------------------------------------------------------------------------
__global__ void __launch_bounds__(THREADS) main_kernel(const float* __restrict__ X) {
    const int m = blockIdx.x / CHUNKS;
    const int chunk = blockIdx.x % CHUNKS;

    __shared__ ull sp[K * PSTRIDE];
    for (int t = threadIdx.x; t < K * PSTRIDE; t += THREADS)
        sp[t] = g_params2[m * K * PSTRIDE + t];
    __syncthreads();

    const float4* __restrict__ X4 = reinterpret_cast<const float4*>(X);

    float acc = 0.f;  // log2-domain accumulator
    const int base = chunk * (N_POINTS / CHUNKS);

    #pragma unroll 1
    for (int it = 0; it < ITERS; ++it) {
        const int n0 = base + it * (THREADS * PPT) + threadIdx.x;

        // load 4 points, pack as 2 pairs: (n0, n0+256) and (n0+512, n0+768)
        ull xp[2][D];
        #pragma unroll
        for (int pr = 0; pr < 2; ++pr) {
            const int na = n0 + (2 * pr) * THREADS;
            const int nb = n0 + (2 * pr + 1) * THREADS;
            float4 a0 = X4[2 * na], a1 = X4[2 * na + 1];
            float4 b0 = X4[2 * nb], b1 = X4[2 * nb + 1];
            xp[pr][0] = pk2(a0.x, b0.x); xp[pr][1] = pk2(a0.y, b0.y);
            xp[pr][2] = pk2(a0.z, b0.z); xp[pr][3] = pk2(a0.w, b0.w);
            xp[pr][4] = pk2(a1.x, b1.x); xp[pr][5] = pk2(a1.y, b1.y);
            xp[pr][6] = pk2(a1.z, b1.z); xp[pr][7] = pk2(a1.w, b1.w);
        }

        float mx[PPT], sm[PPT];
        #pragma unroll
        for (int p = 0; p < PPT; ++p) { mx[p] = -CUDART_INF_F; sm[p] = 0.f; }

        #pragma unroll 1
        for (int k = 0; k < K; ++k) {
            const ull* w = sp + k * PSTRIDE;
            ull wl[TRI], wm[D];
            #pragma unroll
            for (int q = 0; q < TRI; ++q) wl[q] = w[q];
            #pragma unroll
            for (int q = 0; q < D; ++q) wm[q] = w[TRI + q];
            float c, chi;
            up2(w[TRI + D], c, chi);

            #pragma unroll
            for (int pr = 0; pr < 2; ++pr) {
                ull d[D];
                #pragma unroll
                for (int i = 0; i < D; ++i) d[i] = add2p(xp[pr][i], wm[i]);
                ull maha = 0ull;  // bits of {0.f, 0.f}
                #pragma unroll
                for (int i = 0; i < D; ++i) {
                    ull a = mul2p(wl[tidx(i, 0)], d[0]);
                    #pragma unroll
                    for (int j = 1; j <= i; ++j)
                        a = fma2(wl[tidx(i, j)], d[j], a);
                    maha = fma2(a, a, maha);
                }
                float m0, m1;
                up2(maha, m0, m1);
                const float l0 = c - m0;
                const float l1 = c - m1;
                // streaming logsumexp (log2 domain), two points
                {
                    const int p = 2 * pr;
                    float nm = fmaxf(mx[p], l0);
                    sm[p] = fmaf(sm[p], ex2a(mx[p] - nm), ex2a(l0 - nm));
                    mx[p] = nm;
                }
                {
                    const int p = 2 * pr + 1;
                    float nm = fmaxf(mx[p], l1);
                    sm[p] = fmaf(sm[p], ex2a(mx[p] - nm), ex2a(l1 - nm));
                    mx[p] = nm;
                }
            }
        }

        #pragma unroll
        for (int p = 0; p < PPT; ++p)
            acc += mx[p] + lg2a(sm[p]);
    }

    acc *= 0.6931471805599453f;  // back to natural log

    // deterministic block reduction
    __shared__ float red[THREADS];
    red[threadIdx.x] = acc;
    __syncthreads();
    #pragma unroll
    for (int s = THREADS / 2; s > 0; s >>= 1) {
        if (threadIdx.x < s) red[threadIdx.x] += red[threadIdx.x + s];
        __syncthreads();
    }
    if (threadIdx.x == 0) g_partial[m * CHUNKS + chunk] = red[0];
}

// ---------------------------------------------------------------------------
// Finalize: out[m] = -sum_chunks partial + 0.5*LAMBDA_PRIOR * prior[m]
// ---------------------------------------------------------------------------
__global__ void finalize_kernel(float* __restrict__ out) {
    const int m = threadIdx.x;
    if (m < M_MODELS) {
        double s = 0.0;
        #pragma unroll
        for (int c = 0; c < CHUNKS; ++c) s += (double)g_partial[m * CHUNKS + c];
        out[m] = (float)(-s + 0.005 * (double)g_prior[m]);
    }
}

extern "C" void kernel_launch(void* const* d_in, const int* in_sizes, int n_in,
                              void* d_out, int out_size) {
    const float* phi = (const float*)d_in[0];  // (32, 360)
    const float* X   = (const float*)d_in[1];  // (32768, 8)
    float* out = (float*)d_out;                // (32,)

    precompute_kernel<<<M_MODELS, 64>>>(phi);
    main_kernel<<<M_MODELS * CHUNKS, THREADS>>>(X);
    finalize_kernel<<<1, 32>>>(out);
}

// round 3
// speedup vs baseline: 1.2369x; 1.1232x over previous
#include <cuda_runtime.h>
#include <math_constants.h>

#define K 8
#define D 8
#define TRI 36              // D*(D+1)/2
#define PHI_DIM 360         // K + K*D + K*TRI
#define M_MODELS 32
#define N_POINTS 32768
#define CHUNKS 16
#define THREADS 256
#define NPAIR 4             // 4 packed pairs = 8 points per thread
#define PSTRIDE 45          // per-(m,k): 36 Linv + 8 (-Linv*mu bias) + 1 const

typedef unsigned long long ull;

// Scratch (no allocations allowed)
__device__ float g_partial[M_MODELS * CHUNKS];
__device__ int   g_count[M_MODELS];          // zero-init; self-resetting

__host__ __device__ __forceinline__ constexpr int tidx(int i, int j) {
    return i * (i + 1) / 2 + j;
}

// ---- packed f32x2 helpers ---------------------------------------------------
__device__ __forceinline__ ull pk2(float lo, float hi) {
    ull r; asm("mov.b64 %0,{%1,%2};" : "=l"(r) : "f"(lo), "f"(hi)); return r;
}
__device__ __forceinline__ void up2(ull v, float& lo, float& hi) {
    asm("mov.b64 {%0,%1},%2;" : "=f"(lo), "=f"(hi) : "l"(v));
}
__device__ __forceinline__ ull fma2(ull a, ull b, ull c) {
    ull r; asm("fma.rn.f32x2 %0,%1,%2,%3;" : "=l"(r) : "l"(a), "l"(b), "l"(c)); return r;
}
__device__ __forceinline__ float ex2a(float x) {
    float r; asm("ex2.approx.ftz.f32 %0,%1;" : "=f"(r) : "f"(x)); return r;
}
__device__ __forceinline__ float lg2a(float x) {
    float r; asm("lg2.approx.ftz.f32 %0,%1;" : "=f"(r) : "f"(x)); return r;
}

// ---------------------------------------------------------------------------
// Single fused kernel. grid = M_MODELS*CHUNKS = 512 blocks x 256 threads.
// Stage A: block redundantly builds its model's params in shared (threads 0-63
//          do the triangular inversion column-parallel; all threads do prior).
// Stage B: 8 points/thread as 4 packed f32x2 pairs; bias-folded maha; streaming
//          logsumexp in log2 domain with raw MUFU ex2/lg2.
// Stage C: block reduction; last-arriving block per model finalizes (fixed-order
//          deterministic sum) and resets the ticket counter.
// ---------------------------------------------------------------------------
__global__ void __launch_bounds__(THREADS) fused_kernel(const float* __restrict__ phi,
                                                        const float* __restrict__ X,
                                                        float* __restrict__ out) {
    const int m = blockIdx.x >> 4;
    const int chunk = blockIdx.x & (CHUNKS - 1);
    const int tid = threadIdx.x;
    const float* pm = phi + m * PHI_DIM;

    __shared__ ull sp[K * PSTRIDE];
    __shared__ float red[THREADS];
    __shared__ float redp[THREADS];

    // ---- prior partial (all threads; phi is L2-resident after first block) --
    float pp = 0.f;
    #pragma unroll
    for (int i = tid; i < PHI_DIM; i += THREADS) {
        float v = pm[i];
        pp = fmaf(v, v, pp);
    }
    redp[tid] = pp;

    // ---- Stage A: params -----------------------------------------------------
    if (tid < 64) {
        const int k = tid >> 3;
        const int j = tid & 7;
        const float* Lk = pm + K + K * D + k * TRI;
        ull* dst = sp + k * PSTRIDE;
        const float SCALE = 0.8493218002880191f;  // sqrt(0.5*log2(e))

        // column-j forward substitution of the triangular inverse
        float col[D];
        col[j] = __fdividef(1.f, Lk[tidx(j, j)]);
        for (int i = j + 1; i < D; ++i) {
            float acc = 0.f;
            for (int p = j; p < i; ++p)
                acc = fmaf(Lk[tidx(i, p)], col[p], acc);
            col[i] = -acc * __fdividef(1.f, Lk[tidx(i, i)]);
        }
        for (int i = j; i < D; ++i) {
            float v = col[i] * SCALE;
            dst[tidx(i, j)] = pk2(v, v);
        }

        // per-component constant (log2 domain)
        if (j == 0) {
            float mx = -CUDART_INF_F;
            #pragma unroll
            for (int q = 0; q < K; ++q) mx = fmaxf(mx, pm[q]);
            float s = 0.f;
            #pragma unroll
            for (int q = 0; q < K; ++q) s += __expf(pm[q] - mx);
            const float log_pi = pm[k] - mx - __logf(s);

            float ld = 0.f;
            #pragma unroll
            for (int i = 0; i < D; ++i)
                ld += __logf(fmaxf(fabsf(Lk[tidx(i, i)]), 1e-8f));
            ld *= 2.f;

            const float c = log_pi - 0.5f * (D * 1.8378770664093453f + ld);
            const float c2 = c * 1.4426950408889634f;
            dst[TRI + D] = pk2(c2, c2);
        }
    }
    __syncthreads();

    // bias: nb_i = -sum_{j<=i} Linv_scaled[i][j] * mu[j]  (thread (k,i))
    if (tid < 64) {
        const int k = tid >> 3;
        const int i = tid & 7;
        const float* mu = pm + K + k * D;
        ull* dst = sp + k * PSTRIDE;
        float b = 0.f;
        for (int j = 0; j <= i; ++j) {
            float lo, hi;
            up2(dst[tidx(i, j)], lo, hi);
            b = fmaf(lo, mu[j], b);
        }
        float nb = -b;
        dst[TRI + i] = pk2(nb, nb);
    }
    __syncthreads();

    // ---- Stage B: main loop --------------------------------------------------
    const float4* __restrict__ X4 = reinterpret_cast<const float4*>(X);
    const int n0 = chunk * (N_POINTS / CHUNKS) + tid;

    // 8 points packed as 4 pairs: (n0+0,+256), (+512,+768), (+1024,+1280), (+1536,+1792)
    ull xp[NPAIR][D];
    #pragma unroll
    for (int pr = 0; pr < NPAIR; ++pr) {
        const int na = n0 + (2 * pr) * THREADS;
        const int nb = na + THREADS;
        float4 a0 = X4[2 * na], a1 = X4[2 * na + 1];
        float4 b0 = X4[2 * nb], b1 = X4[2 * nb + 1];
        xp[pr][0] = pk2(a0.x, b0.x); xp[pr][1] = pk2(a0.y, b0.y);
        xp[pr][2] = pk2(a0.z, b0.z); xp[pr][3] = pk2(a0.w, b0.w);
        xp[pr][4] = pk2(a1.x, b1.x); xp[pr][5] = pk2(a1.y, b1.y);
        xp[pr][6] = pk2(a1.z, b1.z); xp[pr][7] = pk2(a1.w, b1.w);
    }

    float mx[2 * NPAIR], sm[2 * NPAIR];
    #pragma unroll
    for (int p = 0; p < 2 * NPAIR; ++p) { mx[p] = -CUDART_INF_F; sm[p] = 0.f; }

    #pragma unroll 1
    for (int k = 0; k < K; ++k) {
        const ull* __restrict__ w = sp + k * PSTRIDE;
        float c2, c2h;
        up2(w[TRI + D], c2, c2h);

        ull maha[NPAIR] = {0ull, 0ull, 0ull, 0ull};
        #pragma unroll
        for (int i = 0; i < D; ++i) {
            const ull nb = w[TRI + i];
            ull a0 = nb, a1 = nb, a2 = nb, a3 = nb;
            #pragma unroll
            for (int j = 0; j <= i; ++j) {
                const ull wv = w[tidx(i, j)];
                a0 = fma2(wv, xp[0][j], a0);
                a1 = fma2(wv, xp[1][j], a1);
                a2 = fma2(wv, xp[2][j], a2);
                a3 = fma2(wv, xp[3][j], a3);
            }
            maha[0] = fma2(a0, a0, maha[0]);
            maha[1] = fma2(a1, a1, maha[1]);
            maha[2] = fma2(a2, a2, maha[2]);
            maha[3] = fma2(a3, a3, maha[3]);
        }

        #pragma unroll
        for (int pr = 0; pr < NPAIR; ++pr) {
            float m0, m1;
            up2(maha[pr], m0, m1);
            const float l0 = c2 - m0;
            const float l1 = c2 - m1;
            {
                const int p = 2 * pr;
                const float nm = fmaxf(mx[p], l0);
                sm[p] = fmaf(sm[p], ex2a(mx[p] - nm), ex2a(l0 - nm));
                mx[p] = nm;
            }
            {
                const int p = 2 * pr + 1;
                const float nm = fmaxf(mx[p], l1);
                sm[p] = fmaf(sm[p], ex2a(mx[p] - nm), ex2a(l1 - nm));
                mx[p] = nm;
            }
        }
    }

    float acc = 0.f;
    #pragma unroll
    for (int p = 0; p < 2 * NPAIR; ++p)
        acc += mx[p] + lg2a(sm[p]);
    acc *= 0.6931471805599453f;  // back to natural log

    // ---- Stage C: reduce + finalize -----------------------------------------
    red[tid] = acc;
    __syncthreads();
    #pragma unroll
    for (int s = THREADS / 2; s > 0; s >>= 1) {
        if (tid < s) {
            red[tid] += red[tid + s];
            redp[tid] += redp[tid + s];
        }
        __syncthreads();
    }

    if (tid == 0) {
        g_partial[m * CHUNKS + chunk] = red[0];
        __threadfence();
        const int old = atomicAdd(&g_count[m], 1);
        if (old == CHUNKS - 1) {
            __threadfence();
            double s = 0.0;
            #pragma unroll
            for (int c = 0; c < CHUNKS; ++c)
                s += (double)__ldcg(&g_partial[m * CHUNKS + c]);
            out[m] = (float)(-s + 0.005 * (double)redp[0]);  // 0.5*LAMBDA_PRIOR
            g_count[m] = 0;  // self-reset for next launch
        }
    }
}

extern "C" void kernel_launch(void* const* d_in, const int* in_sizes, int n_in,
                              void* d_out, int out_size) {
    const float* phi = (const float*)d_in[0];  // (32, 360)
    const float* X   = (const float*)d_in[1];  // (32768, 8)
    float* out = (float*)d_out;                // (32,)

    fused_kernel<<<M_MODELS * CHUNKS, THREADS>>>(phi, X, out);
}

// round 4
// speedup vs baseline: 1.3241x; 1.0706x over previous
#include <cuda_runtime.h>
#include <math_constants.h>

#define K 8
#define D 8
#define TRI 36              // D*(D+1)/2
#define PHI_DIM 360         // K + K*D + K*TRI
#define M_MODELS 32
#define N_POINTS 32768
#define CHUNKS 32
#define THREADS 256
#define NPAIR 2             // 2 packed pairs = 4 points per thread
#define PSTRIDE 46          // 36 Linv + 8 bias + 1 const + 1 pad (16B-aligned)

typedef unsigned long long ull;

// Scratch (no allocations allowed)
__device__ float g_partial[M_MODELS * CHUNKS];
__device__ int   g_count[M_MODELS];          // zero-init; self-resetting

__host__ __device__ __forceinline__ constexpr int tidx(int i, int j) {
    return i * (i + 1) / 2 + j;
}

// ---- packed f32x2 helpers ---------------------------------------------------
__device__ __forceinline__ ull pk2(float lo, float hi) {
    ull r; asm("mov.b64 %0,{%1,%2};" : "=l"(r) : "f"(lo), "f"(hi)); return r;
}
__device__ __forceinline__ void up2(ull v, float& lo, float& hi) {
    asm("mov.b64 {%0,%1},%2;" : "=f"(lo), "=f"(hi) : "l"(v));
}
__device__ __forceinline__ ull fma2(ull a, ull b, ull c) {
    ull r; asm("fma.rn.f32x2 %0,%1,%2,%3;" : "=l"(r) : "l"(a), "l"(b), "l"(c)); return r;
}
__device__ __forceinline__ float ex2a(float x) {
    float r; asm("ex2.approx.ftz.f32 %0,%1;" : "=f"(r) : "f"(x)); return r;
}
__device__ __forceinline__ float lg2a(float x) {
    float r; asm("lg2.approx.ftz.f32 %0,%1;" : "=f"(r) : "f"(x)); return r;
}

// ---------------------------------------------------------------------------
// Single fused kernel. grid = M_MODELS*CHUNKS = 1024 blocks x 256 threads,
// capped at 64 regs for 4 CTAs/SM (8 warps per scheduler -> latency hiding).
// ---------------------------------------------------------------------------
__global__ void __launch_bounds__(THREADS, 4) fused_kernel(const float* __restrict__ phi,
                                                           const float* __restrict__ X,
                                                           float* __restrict__ out) {
    const int m = blockIdx.x >> 5;
    const int chunk = blockIdx.x & (CHUNKS - 1);
    const int tid = threadIdx.x;
    const float* pm = phi + m * PHI_DIM;

    __shared__ ull sp[K * PSTRIDE];
    __shared__ float red[THREADS];
    __shared__ float redp[THREADS];

    // ---- prior partial -------------------------------------------------------
    float pp = 0.f;
    #pragma unroll
    for (int i = tid; i < PHI_DIM; i += THREADS) {
        float v = pm[i];
        pp = fmaf(v, v, pp);
    }
    redp[tid] = pp;

    // ---- Stage A: build params in shared (threads 0-63, column-parallel) ----
    if (tid < 64) {
        const int k = tid >> 3;
        const int j = tid & 7;
        const float* Lk = pm + K + K * D + k * TRI;
        ull* dst = sp + k * PSTRIDE;
        const float SCALE = 0.8493218002880191f;  // sqrt(0.5*log2(e))

        float col[D];
        col[j] = __fdividef(1.f, Lk[tidx(j, j)]);
        for (int i = j + 1; i < D; ++i) {
            float acc = 0.f;
            for (int p = j; p < i; ++p)
                acc = fmaf(Lk[tidx(i, p)], col[p], acc);
            col[i] = -acc * __fdividef(1.f, Lk[tidx(i, i)]);
        }
        for (int i = j; i < D; ++i) {
            float v = col[i] * SCALE;
            dst[tidx(i, j)] = pk2(v, v);
        }

        if (j == 0) {
            float mx = -CUDART_INF_F;
            #pragma unroll
            for (int q = 0; q < K; ++q) mx = fmaxf(mx, pm[q]);
            float s = 0.f;
            #pragma unroll
            for (int q = 0; q < K; ++q) s += __expf(pm[q] - mx);
            const float log_pi = pm[k] - mx - __logf(s);

            float ld = 0.f;
            #pragma unroll
            for (int i = 0; i < D; ++i)
                ld += __logf(fmaxf(fabsf(Lk[tidx(i, i)]), 1e-8f));
            ld *= 2.f;

            const float c = log_pi - 0.5f * (D * 1.8378770664093453f + ld);
            const float c2 = c * 1.4426950408889634f;
            dst[TRI + D] = pk2(c2, c2);
            dst[TRI + D + 1] = 0ull;  // pad
        }
    }
    __syncthreads();

    // bias: nb_i = -sum_{j<=i} Linv_scaled[i][j] * mu[j]
    if (tid < 64) {
        const int k = tid >> 3;
        const int i = tid & 7;
        const float* mu = pm + K + k * D;
        ull* dst = sp + k * PSTRIDE;
        float b = 0.f;
        for (int j = 0; j <= i; ++j) {
            float lo, hi;
            up2(dst[tidx(i, j)], lo, hi);
            b = fmaf(lo, mu[j], b);
        }
        float nb = -b;
        dst[TRI + i] = pk2(nb, nb);
    }
    __syncthreads();

    // ---- Stage B: main loop --------------------------------------------------
    const float4* __restrict__ X4 = reinterpret_cast<const float4*>(X);
    const int n0 = chunk * (N_POINTS / CHUNKS) + tid;

    // 4 points as 2 pairs: (n0, n0+256), (n0+512, n0+768)
    ull xp[NPAIR][D];
    #pragma unroll
    for (int pr = 0; pr < NPAIR; ++pr) {
        const int na = n0 + (2 * pr) * THREADS;
        const int nb = na + THREADS;
        float4 a0 = X4[2 * na], a1 = X4[2 * na + 1];
        float4 b0 = X4[2 * nb], b1 = X4[2 * nb + 1];
        xp[pr][0] = pk2(a0.x, b0.x); xp[pr][1] = pk2(a0.y, b0.y);
        xp[pr][2] = pk2(a0.z, b0.z); xp[pr][3] = pk2(a0.w, b0.w);
        xp[pr][4] = pk2(a1.x, b1.x); xp[pr][5] = pk2(a1.y, b1.y);
        xp[pr][6] = pk2(a1.z, b1.z); xp[pr][7] = pk2(a1.w, b1.w);
    }

    float mx[2 * NPAIR], sm[2 * NPAIR];
    #pragma unroll
    for (int p = 0; p < 2 * NPAIR; ++p) { mx[p] = -CUDART_INF_F; sm[p] = 0.f; }

    #pragma unroll 1
    for (int k = 0; k < K; ++k) {
        const ull* __restrict__ w = sp + k * PSTRIDE;
        float c2, c2h;
        up2(w[TRI + D], c2, c2h);

        ull maha[NPAIR] = {0ull, 0ull};
        #pragma unroll
        for (int i = 0; i < D; ++i) {
            const ull nb = w[TRI + i];
            ull a0 = nb, a1 = nb;
            #pragma unroll
            for (int j = 0; j <= i; ++j) {
                const ull wv = w[tidx(i, j)];
                a0 = fma2(wv, xp[0][j], a0);
                a1 = fma2(wv, xp[1][j], a1);
            }
            maha[0] = fma2(a0, a0, maha[0]);
            maha[1] = fma2(a1, a1, maha[1]);
        }

        #pragma unroll
        for (int pr = 0; pr < NPAIR; ++pr) {
            float m0, m1;
            up2(maha[pr], m0, m1);
            const float l0 = c2 - m0;
            const float l1 = c2 - m1;
            {
                const int p = 2 * pr;
                const float nm = fmaxf(mx[p], l0);
                sm[p] = fmaf(sm[p], ex2a(mx[p] - nm), ex2a(l0 - nm));
                mx[p] = nm;
            }
            {
                const int p = 2 * pr + 1;
                const float nm = fmaxf(mx[p], l1);
                sm[p] = fmaf(sm[p], ex2a(mx[p] - nm), ex2a(l1 - nm));
                mx[p] = nm;
            }
        }
    }

    float acc = 0.f;
    #pragma unroll
    for (int p = 0; p < 2 * NPAIR; ++p)
        acc += mx[p] + lg2a(sm[p]);
    acc *= 0.6931471805599453f;  // back to natural log

    // ---- Stage C: reduce + finalize -----------------------------------------
    red[tid] = acc;
    __syncthreads();
    #pragma unroll
    for (int s = THREADS / 2; s > 0; s >>= 1) {
        if (tid < s) {
            red[tid] += red[tid + s];
            redp[tid] += redp[tid + s];
        }
        __syncthreads();
    }

    if (tid == 0) {
        g_partial[m * CHUNKS + chunk] = red[0];
        __threadfence();
        const int old = atomicAdd(&g_count[m], 1);
        if (old == CHUNKS - 1) {
            __threadfence();
            double s = 0.0;
            #pragma unroll
            for (int c = 0; c < CHUNKS; ++c)
                s += (double)__ldcg(&g_partial[m * CHUNKS + c]);
            out[m] = (float)(-s + 0.005 * (double)redp[0]);  // 0.5*LAMBDA_PRIOR
            g_count[m] = 0;  // self-reset for next launch
        }
    }
}

extern "C" void kernel_launch(void* const* d_in, const int* in_sizes, int n_in,
                              void* d_out, int out_size) {
    const float* phi = (const float*)d_in[0];  // (32, 360)
    const float* X   = (const float*)d_in[1];  // (32768, 8)
    float* out = (float*)d_out;                // (32,)

    fused_kernel<<<M_MODELS * CHUNKS, THREADS>>>(phi, X, out);
}